// round 8
// baseline (speedup 1.0000x reference)
#include <cuda_runtime.h>
#include <cuda_fp16.h>
#include <cstdint>

#define BB 8
#define CC 16
#define FDIM 256
#define F2 129
#define TT 512
#define C2 32
#define HH 16
#define NT (BB*TT)

// ---------------- device scratch ----------------
__device__ float g_zraw[(size_t)BB*C2*F2*TT];   // spectrum planes (b, c2, k, t): re c=0..15, im c=16..31
__device__ __half g_pre16[(size_t)NT*F2*128];   // gate preactivations fp16 (n, k, 128)
__device__ float g_h   [(size_t)NT*F2*C2];      // LSTM hidden cat(fwd,bwd): (n, k, 2H)
__device__ float g_P   [(size_t)BB*C2*F2*TT];   // product spectrum planes
__device__ float g_mean[NT];
__device__ float g_rstd[NT];
__device__ float g_psum[NT*6];
__device__ float g_psq [NT*6];

__device__ __forceinline__ float sigf(float x) {
    return __fdividef(1.f, 1.f + __expf(-x));
}
__device__ __forceinline__ float tanhfast(float x) {
    return fmaf(2.f, __fdividef(1.f, 1.f + __expf(-2.f * x)), -1.f);
}
__device__ __forceinline__ unsigned long long pack2(float a, float b) {
    unsigned long long r;
    asm("mov.b64 %0, {%1,%2};" : "=l"(r) : "r"(__float_as_uint(a)), "r"(__float_as_uint(b)));
    return r;
}
__device__ __forceinline__ void unpack2(unsigned long long v, float& a, float& b) {
    unsigned int lo, hi;
    asm("mov.b64 {%0,%1}, %2;" : "=r"(lo), "=r"(hi) : "l"(v));
    a = __uint_as_float(lo); b = __uint_as_float(hi);
}
__device__ __forceinline__ unsigned long long ffma2(unsigned long long a, unsigned long long b, unsigned long long c) {
    unsigned long long d;
    asm("fma.rn.f32x2 %0, %1, %2, %3;" : "=l"(d) : "l"(a), "l"(b), "l"(c));
    return d;
}
__device__ __forceinline__ int dr4(int k) {   // base-4 digit reversal, 4 digits
    return ((k & 3) << 6) | (((k >> 2) & 3) << 4) | (((k >> 4) & 3) << 2) | ((k >> 6) & 3);
}

// ---------------- K1: forward rfft, warp-private radix-4, real-pair packed --
// grid (128, 16), block 512 (16 warps). 32 t-cols -> 16 complex FFTs, one/warp.
__global__ void __launch_bounds__(512) k_fft_fwd(const float* __restrict__ x) {
    int bc = blockIdx.x;
    int t0 = blockIdx.y * 32;
    int b = bc >> 4, c = bc & 15;
    __shared__ float sr[258][17], si[258][17];
    __shared__ float2 tw[192];
    int tid = threadIdx.x;
    int w = tid >> 5, l = tid & 31;

    if (tid < 192) {
        float sv, cv;
        __sincosf(-6.28318530717958647692f * (float)tid * (1.f / 256.f), &sv, &cv);
        tw[tid] = make_float2(cv, sv);
    }
    for (int i = tid; i < 8192; i += 512) {
        int f = i >> 5, tt = i & 31;
        float v = x[((size_t)bc * 256 + f) * 512 + t0 + tt];
        if (tt & 1) si[f][tt >> 1] = v; else sr[f][tt >> 1] = v;
    }
    __syncthreads();

    #pragma unroll
    for (int stage = 0; stage < 4; ++stage) {
        int ms = 6 - 2 * stage;
        int m = 1 << ms;
        #pragma unroll
        for (int half = 0; half < 2; ++half) {
            int bfy = l + 32 * half;
            int g = bfy >> ms, p = bfy & (m - 1);
            int base = (g << (ms + 2)) + p;
            int e1 = p << (2 * stage);
            float2 w1 = tw[e1], w2 = tw[2 * e1], w3 = tw[3 * e1];
            float ar = sr[base][w],        ai = si[base][w];
            float br = sr[base + m][w],    bi = si[base + m][w];
            float cr = sr[base + 2*m][w],  ci = si[base + 2*m][w];
            float dr = sr[base + 3*m][w],  di = si[base + 3*m][w];
            float t0r = ar + cr, t0i = ai + ci;
            float t1r = ar - cr, t1i = ai - ci;
            float t2r = br + dr, t2i = bi + di;
            float t3r = br - dr, t3i = bi - di;
            sr[base][w] = t0r + t2r;  si[base][w] = t0i + t2i;
            float u1r = t1r + t3i, u1i = t1i - t3r;
            sr[base + m][w]   = u1r * w1.x - u1i * w1.y;
            si[base + m][w]   = u1r * w1.y + u1i * w1.x;
            float v2r = t0r - t2r, v2i = t0i - t2i;
            sr[base + 2*m][w] = v2r * w2.x - v2i * w2.y;
            si[base + 2*m][w] = v2r * w2.y + v2i * w2.x;
            float u3r = t1r - t3i, u3i = t1i + t3r;
            sr[base + 3*m][w] = u3r * w3.x - u3i * w3.y;
            si[base + 3*m][w] = u3r * w3.y + u3i * w3.x;
        }
        __syncwarp();
    }

    float va[5][4];
    #pragma unroll
    for (int r = 0; r < 4; ++r) {
        int k = l + 32 * r;
        int ik = dr4(k), im = dr4((256 - k) & 255);
        float zkr = sr[ik][w], zki = si[ik][w];
        float zmr = sr[im][w], zmi = si[im][w];
        va[r][0] = 0.5f * (zkr + zmr);
        va[r][1] = 0.5f * (zki - zmi);
        va[r][2] = 0.5f * (zki + zmi);
        va[r][3] = 0.5f * (zmr - zkr);
    }
    if (l == 0) {
        int ik = dr4(128);
        float zkr = sr[ik][w], zki = si[ik][w];
        va[4][0] = zkr; va[4][1] = 0.f;
        va[4][2] = zki; va[4][3] = 0.f;
    }
    __syncwarp();
    #pragma unroll
    for (int r = 0; r < 4; ++r) {
        int k = l + 32 * r;
        sr[k][w] = va[r][0];        si[k][w] = va[r][1];
        sr[129 + k][w] = va[r][2];  si[129 + k][w] = va[r][3];
    }
    if (l == 0) {
        sr[128][w] = va[4][0];       si[128][w] = va[4][1];
        sr[129 + 128][w] = va[4][2]; si[129 + 128][w] = va[4][3];
    }
    __syncthreads();

    for (int i = tid; i < 4128; i += 512) {
        int k = i >> 5, tt = i & 31;
        int j = tt >> 1;
        int row = (tt & 1) ? (129 + k) : k;
        g_zraw[(((size_t)b * 32 + c)      * 129 + k) * 512 + t0 + tt] = sr[row][j];
        g_zraw[(((size_t)b * 32 + 16 + c) * 129 + k) * 512 + t0 + tt] = si[row][j];
    }
}

// ---------------- K2a: partial stats, grid (8,16,6), block 512 --------------
__global__ void k_stats1() {
    __shared__ float s_sum[16][32], s_sq[16][32];
    int w = threadIdx.x >> 5, l = threadIdx.x & 31;
    int b = blockIdx.x;
    int t = blockIdx.y * 32 + l;
    int part = blockIdx.z;
    const float* base = g_zraw + (size_t)b * 4128 * 512 + t;
    float sum = 0.f, sq = 0.f;
    int e0 = part * 688 + w * 43;
    #pragma unroll 4
    for (int e = e0; e < e0 + 43; ++e) {
        float v = base[(size_t)e * 512];
        sum += v; sq = fmaf(v, v, sq);
    }
    s_sum[w][l] = sum; s_sq[w][l] = sq;
    __syncthreads();
    if (threadIdx.x < 32) {
        int n = b * 512 + blockIdx.y * 32 + threadIdx.x;
        float S = 0.f, Q = 0.f;
        #pragma unroll
        for (int i = 0; i < 16; ++i) { S += s_sum[i][threadIdx.x]; Q += s_sq[i][threadIdx.x]; }
        g_psum[n * 6 + part] = S;
        g_psq [n * 6 + part] = Q;
    }
}

// ---------------- K2b: finalize stats ---------------------------------------
__global__ void k_stats2() {
    int n = blockIdx.x * 256 + threadIdx.x;
    float S = 0.f, Q = 0.f;
    #pragma unroll
    for (int p = 0; p < 6; ++p) { S += g_psum[n * 6 + p]; Q += g_psq[n * 6 + p]; }
    float mean = S * (1.f / 4128.f);
    float var = (Q - S * mean) * (1.f / 4127.f);
    g_mean[n] = mean;
    g_rstd[n] = __fdividef(1.f, sqrtf(fmaxf(var, 0.f)) + 1e-8f);
}

// ---------------- K3: normalize + input-gate GEMM, warp-row outer product ---
// grid (129, 64), block 256 (8 warps). Block: one k, 64 t.
// Warp: 8 t; lane: 4 adjacent gates (natural u64 weight pairs from smem).
__global__ void __launch_bounds__(256) k_gates(
    const float* __restrict__ nw, const float* __restrict__ nb,
    const float* __restrict__ wihf, const float* __restrict__ bihf, const float* __restrict__ bhhf,
    const float* __restrict__ wihb, const float* __restrict__ bihb, const float* __restrict__ bhhb) {
    int k = blockIdx.x;
    int n0 = blockIdx.y * 64;
    int b = n0 >> 9, tl0 = n0 & 511;
    __shared__ __align__(16) float ys[32][68];     // [q][t], pitch 272B (16B mult)
    __shared__ __align__(16) float ws[32][132];    // [q][gate], pitch 528B (16B mult)
    __shared__ __align__(16) float bs[128];
    __shared__ float nws[32], nbs[32], means[64], rstds[64];
    int tid = threadIdx.x;

    for (int i = tid; i < 2048; i += 256) {
        int c2 = i >> 6, tt = i & 63;
        ys[c2][tt] = g_zraw[(((size_t)b * 32 + c2) * 129 + k) * 512 + tl0 + tt];
    }
    for (int i = tid; i < 4096; i += 256) {
        int q = i >> 7, g = i & 127;
        ws[q][g] = (g < 64) ? wihf[g * 32 + q] : wihb[(g - 64) * 32 + q];
    }
    if (tid < 64) bs[tid] = bihf[tid] + bhhf[tid];
    else if (tid < 128) bs[tid] = bihb[tid - 64] + bhhb[tid - 64];
    if (tid < 32) { nws[tid] = nw[tid * 129 + k]; nbs[tid] = nb[tid * 129 + k]; }
    if (tid >= 128 && tid < 192) { means[tid - 128] = g_mean[n0 + tid - 128]; rstds[tid - 128] = g_rstd[n0 + tid - 128]; }
    __syncthreads();

    for (int i = tid; i < 2048; i += 256) {
        int c2 = i >> 6, tt = i & 63;
        ys[c2][tt] = (ys[c2][tt] - means[tt]) * rstds[tt] * nws[c2] + nbs[c2];
    }
    __syncthreads();

    int wid = tid >> 5, l = tid & 31;
    int t8 = wid << 3;          // warp's 8 t-points
    int g0 = l << 2;            // lane's 4 gates
    unsigned long long acc[8][2];
    unsigned long long b01 = *reinterpret_cast<const unsigned long long*>(&bs[g0]);
    unsigned long long b23 = *reinterpret_cast<const unsigned long long*>(&bs[g0 + 2]);
    #pragma unroll
    for (int t = 0; t < 8; ++t) { acc[t][0] = b01; acc[t][1] = b23; }

    #pragma unroll 4
    for (int q = 0; q < 32; ++q) {
        ulonglong2 wv = *reinterpret_cast<const ulonglong2*>(&ws[q][g0]);  // (w0,w1),(w2,w3)
        float4 ya = *reinterpret_cast<const float4*>(&ys[q][t8]);          // broadcast
        float4 yb = *reinterpret_cast<const float4*>(&ys[q][t8 + 4]);
        unsigned long long yy[8];
        yy[0] = pack2(ya.x, ya.x); yy[1] = pack2(ya.y, ya.y);
        yy[2] = pack2(ya.z, ya.z); yy[3] = pack2(ya.w, ya.w);
        yy[4] = pack2(yb.x, yb.x); yy[5] = pack2(yb.y, yb.y);
        yy[6] = pack2(yb.z, yb.z); yy[7] = pack2(yb.w, yb.w);
        #pragma unroll
        for (int t = 0; t < 8; ++t) {
            acc[t][0] = ffma2(yy[t], wv.x, acc[t][0]);
            acc[t][1] = ffma2(yy[t], wv.y, acc[t][1]);
        }
    }

    // fp16 store: warp row per t = 256B contiguous
    #pragma unroll
    for (int t = 0; t < 8; ++t) {
        float f0, f1, f2, f3;
        unpack2(acc[t][0], f0, f1);
        unpack2(acc[t][1], f2, f3);
        __half2 h01 = __floats2half2_rn(f0, f1);
        __half2 h23 = __floats2half2_rn(f2, f3);
        uint2 v;
        v.x = *reinterpret_cast<unsigned int*>(&h01);
        v.y = *reinterpret_cast<unsigned int*>(&h23);
        size_t idx = ((size_t)(n0 + t8 + t) * 129 + k) * 128 + g0;
        *reinterpret_cast<uint2*>(&g_pre16[idx]) = v;
    }
}

// ---------------- K4: recurrent-only LSTM, one warp per (seq, dir) ----------
__global__ void __launch_bounds__(256) k_lstm(
    const float* __restrict__ whhf, const float* __restrict__ whhb) {
    int wg = blockIdx.x * 8 + (threadIdx.x >> 5);
    int lane = threadIdx.x & 31;
    int n = wg >> 1, dir = wg & 1;

    const float* whh = dir ? whhb : whhf;
    float wh0[16], wh1[16];
    #pragma unroll
    for (int q = 0; q < 16; ++q) {
        wh0[q] = whh[lane * 16 + q];
        wh1[q] = whh[(lane + 32) * 16 + q];
    }

    const __half* pbase = g_pre16 + (size_t)n * 129 * 128 + dir * 64;
    float* hbase = g_h + (size_t)n * 129 * 32 + dir * 16;

    float h = 0.f, cst = 0.f;
    int k = dir ? 128 : 0;
    int stepd = dir ? -1 : 1;
    float p0 = __half2float(pbase[k * 128 + lane]);
    float p1 = __half2float(pbase[k * 128 + 32 + lane]);

    for (int s = 0; s < 129; ++s) {
        int kn = k + stepd;
        float np0 = 0.f, np1 = 0.f;
        if (s < 128) {
            np0 = __half2float(pbase[kn * 128 + lane]);
            np1 = __half2float(pbase[kn * 128 + 32 + lane]);
        }
        float a0 = p0, a1 = p1, c0 = 0.f, c1 = 0.f;
        #pragma unroll
        for (int q = 0; q < 8; ++q) {
            float hv = __shfl_sync(0xffffffffu, h, q);
            a0 = fmaf(hv, wh0[q], a0);
            a1 = fmaf(hv, wh1[q], a1);
        }
        #pragma unroll
        for (int q = 8; q < 16; ++q) {
            float hv = __shfl_sync(0xffffffffu, h, q);
            c0 = fmaf(hv, wh0[q], c0);
            c1 = fmaf(hv, wh1[q], c1);
        }
        a0 += c0; a1 += c1;
        float fo0 = __shfl_xor_sync(0xffffffffu, a0, 16);
        float fo1 = __shfl_xor_sync(0xffffffffu, a1, 16);
        if (lane < 16) {
            float ig = sigf(a0);
            float gg = tanhfast(a1);
            float ff = sigf(fo0);
            float oo = sigf(fo1);
            cst = fmaf(ff, cst, ig * gg);
            h = oo * tanhfast(cst);
            hbase[k * 32 + lane] = h;
        }
        p0 = np0; p1 = np1; k = kn;
    }
}

// ---------------- K5: linear(2H->2C) + complex multiply ---------------------
__global__ void k_lin_cmul(const float* __restrict__ lw, const float* __restrict__ lb) {
    int k = blockIdx.x, t0 = blockIdx.y * 32, b = blockIdx.z;
    __shared__ float hs[32][33];    // [t][j]
    __shared__ float lws[32][32];   // [c2][j]
    __shared__ float lbs[32];
    __shared__ float yls[32][33];   // [c2][t]
    int tid = threadIdx.x;

    for (int i = tid; i < 1024; i += 256) lws[i >> 5][i & 31] = lw[i];
    if (tid < 32) lbs[tid] = lb[tid];
    for (int i = tid; i < 1024; i += 256) {
        int tt = i >> 5, j = i & 31;
        hs[tt][j] = g_h[(((size_t)(b * 512 + t0 + tt)) * 129 + k) * 32 + j];
    }
    __syncthreads();

    int tt = tid & 31, g = tid >> 5;
    #pragma unroll
    for (int ci = 0; ci < 4; ++ci) {
        int c2 = g + ci * 8;
        float acc = lbs[c2];
        #pragma unroll
        for (int j = 0; j < 32; ++j) acc = fmaf(hs[tt][j], lws[c2][j], acc);
        yls[c2][tt] = acc;
    }
    __syncthreads();

    size_t basez = ((size_t)(b * 32) * 129 + k) * 512 + t0 + tt;
    const size_t ps = (size_t)129 * 512;
    #pragma unroll
    for (int ci = 0; ci < 4; ++ci) {
        int c2 = g + ci * 8;
        if (c2 < 16) {
            float xr = g_zraw[basez + (size_t)c2 * ps];
            float xi = g_zraw[basez + (size_t)(c2 + 16) * ps];
            float yr = yls[c2][tt], yi = yls[c2 + 16][tt];
            g_P[basez + (size_t)c2 * ps] = yr * xr - yi * xi;
        } else {
            int c = c2 - 16;
            float xr = g_zraw[basez + (size_t)c * ps];
            float xi = g_zraw[basez + (size_t)c2 * ps];
            float yr = yls[c][tt], yi = yls[c2][tt];
            g_P[basez + (size_t)c2 * ps] = yr * xi + yi * xr;
        }
    }
}

// ---------------- K6: irfft, warp-private radix-4, spectrum-pair packed -----
// grid (128, 16), block 512.
__global__ void __launch_bounds__(512) k_fft_inv(float* __restrict__ out) {
    int bc = blockIdx.x;
    int t0 = blockIdx.y * 32;
    int b = bc >> 4, c = bc & 15;
    __shared__ float sr[258][17], si[258][17];
    __shared__ float2 tw[192];
    int tid = threadIdx.x;
    int w = tid >> 5, l = tid & 31;

    if (tid < 192) {
        float sv, cv;
        __sincosf(6.28318530717958647692f * (float)tid * (1.f / 256.f), &sv, &cv);
        tw[tid] = make_float2(cv, sv);
    }
    for (int i = tid; i < 4128; i += 512) {
        int k = i >> 5, tt = i & 31;
        int j = tt >> 1;
        int row = (tt & 1) ? (129 + k) : k;
        sr[row][j] = g_P[(((size_t)b * 32 + c)      * 129 + k) * 512 + t0 + tt];
        si[row][j] = g_P[(((size_t)b * 32 + 16 + c) * 129 + k) * 512 + t0 + tt];
    }
    __syncthreads();

    float vz[8][2];
    #pragma unroll
    for (int r = 0; r < 8; ++r) {
        int row = l + 32 * r;
        float zr, zi;
        if (row <= 128) {
            float par = sr[row][w];
            float pai = (row == 0 || row == 128) ? 0.f : si[row][w];
            float pbr = sr[129 + row][w];
            float pbi = (row == 0 || row == 128) ? 0.f : si[129 + row][w];
            zr = par - pbi; zi = pai + pbr;
        } else {
            int m = 256 - row;
            float par = sr[m][w], pai = si[m][w];
            float pbr = sr[129 + m][w], pbi = si[129 + m][w];
            zr = par + pbi; zi = pbr - pai;
        }
        vz[r][0] = zr; vz[r][1] = zi;
    }
    __syncwarp();
    #pragma unroll
    for (int r = 0; r < 8; ++r) {
        int row = l + 32 * r;
        sr[row][w] = vz[r][0];
        si[row][w] = vz[r][1];
    }
    __syncwarp();

    #pragma unroll
    for (int stage = 0; stage < 4; ++stage) {
        int ms = 6 - 2 * stage;
        int m = 1 << ms;
        #pragma unroll
        for (int half = 0; half < 2; ++half) {
            int bfy = l + 32 * half;
            int g = bfy >> ms, p = bfy & (m - 1);
            int base = (g << (ms + 2)) + p;
            int e1 = p << (2 * stage);
            float2 w1 = tw[e1], w2 = tw[2 * e1], w3 = tw[3 * e1];
            float ar = sr[base][w],        ai = si[base][w];
            float br = sr[base + m][w],    bi = si[base + m][w];
            float cr = sr[base + 2*m][w],  ci = si[base + 2*m][w];
            float dr = sr[base + 3*m][w],  di = si[base + 3*m][w];
            float t0r = ar + cr, t0i = ai + ci;
            float t1r = ar - cr, t1i = ai - ci;
            float t2r = br + dr, t2i = bi + di;
            float t3r = br - dr, t3i = bi - di;
            sr[base][w] = t0r + t2r;  si[base][w] = t0i + t2i;
            float u1r = t1r - t3i, u1i = t1i + t3r;
            sr[base + m][w]   = u1r * w1.x - u1i * w1.y;
            si[base + m][w]   = u1r * w1.y + u1i * w1.x;
            float v2r = t0r - t2r, v2i = t0i - t2i;
            sr[base + 2*m][w] = v2r * w2.x - v2i * w2.y;
            si[base + 2*m][w] = v2r * w2.y + v2i * w2.x;
            float u3r = t1r + t3i, u3i = t1i - t3r;
            sr[base + 3*m][w] = u3r * w3.x - u3i * w3.y;
            si[base + 3*m][w] = u3r * w3.y + u3i * w3.x;
        }
        __syncwarp();
    }
    __syncthreads();

    const float inv = 1.f / 256.f;
    for (int i = tid; i < 8192; i += 512) {
        int f = i >> 5, tt = i & 31;
        int j = tt >> 1;
        int src = dr4(f);
        float v = (tt & 1) ? si[src][j] : sr[src][j];
        out[((size_t)bc * 256 + f) * 512 + t0 + tt] = v * inv;
    }
}

// ---------------- launcher ---------------------------------------------------
extern "C" void kernel_launch(void* const* d_in, const int* in_sizes, int n_in,
                              void* d_out, int out_size) {
    const float* x    = (const float*)d_in[0];
    const float* nw   = (const float*)d_in[1];
    const float* nb   = (const float*)d_in[2];
    const float* wihf = (const float*)d_in[3];
    const float* whhf = (const float*)d_in[4];
    const float* bihf = (const float*)d_in[5];
    const float* bhhf = (const float*)d_in[6];
    const float* wihb = (const float*)d_in[7];
    const float* whhb = (const float*)d_in[8];
    const float* bihb = (const float*)d_in[9];
    const float* bhhb = (const float*)d_in[10];
    const float* lw   = (const float*)d_in[11];
    const float* lb   = (const float*)d_in[12];
    float* out = (float*)d_out;

    k_fft_fwd<<<dim3(128, 16), 512>>>(x);
    k_stats1<<<dim3(8, 16, 6), 512>>>();
    k_stats2<<<16, 256>>>();
    k_gates<<<dim3(129, 64), 256>>>(nw, nb, wihf, bihf, bhhf, wihb, bihb, bhhb);
    k_lstm<<<1024, 256>>>(whhf, whhb);
    k_lin_cmul<<<dim3(129, 16, 8), 256>>>(lw, lb);
    k_fft_inv<<<dim3(128, 16), 512>>>(out);
}

// round 9
// speedup vs baseline: 1.0097x; 1.0097x over previous
#include <cuda_runtime.h>
#include <cstdint>

#define BB 8
#define CC 16
#define FDIM 256
#define F2 129
#define TT 512
#define C2 32
#define HH 16
#define NT (BB*TT)

// ---------------- device scratch ----------------
__device__ float g_zraw[(size_t)BB*C2*F2*TT];   // spectrum planes (b, c2, k, t): re c=0..15, im c=16..31
__device__ float g_pre [(size_t)NT*F2*128];     // gate preacts (n, k, 128): dir*64 + 2*(r&31)+(r>>5)
__device__ float g_h   [(size_t)NT*F2*C2];      // LSTM hidden cat(fwd,bwd): (n, k, 2H)
__device__ float g_P   [(size_t)BB*C2*F2*TT];   // product spectrum planes
__device__ float g_mean[NT];
__device__ float g_rstd[NT];
__device__ float g_psum[NT*6];
__device__ float g_psq [NT*6];

__device__ __forceinline__ float sigf(float x) {
    return __fdividef(1.f, 1.f + __expf(-x));
}
__device__ __forceinline__ float tanhfast(float x) {
    return fmaf(2.f, __fdividef(1.f, 1.f + __expf(-2.f * x)), -1.f);
}
__device__ __forceinline__ unsigned long long pack2(float a, float b) {
    unsigned long long r;
    asm("mov.b64 %0, {%1,%2};" : "=l"(r) : "r"(__float_as_uint(a)), "r"(__float_as_uint(b)));
    return r;
}
__device__ __forceinline__ void unpack2(unsigned long long v, float& a, float& b) {
    unsigned int lo, hi;
    asm("mov.b64 {%0,%1}, %2;" : "=r"(lo), "=r"(hi) : "l"(v));
    a = __uint_as_float(lo); b = __uint_as_float(hi);
}
__device__ __forceinline__ unsigned long long ffma2(unsigned long long a, unsigned long long b, unsigned long long c) {
    unsigned long long d;
    asm("fma.rn.f32x2 %0, %1, %2, %3;" : "=l"(d) : "l"(a), "l"(b), "l"(c));
    return d;
}
__device__ __forceinline__ int dr4(int k) {   // base-4 digit reversal, 4 digits
    return ((k & 3) << 6) | (((k >> 2) & 3) << 4) | (((k >> 4) & 3) << 2) | ((k >> 6) & 3);
}

// ---------------- K1: forward rfft, warp-private radix-4, real-pair packed --
// grid (128, 16), block 512 (16 warps). 32 t-cols -> 16 complex FFTs, one/warp.
__global__ void __launch_bounds__(512) k_fft_fwd(const float* __restrict__ x) {
    int bc = blockIdx.x;
    int t0 = blockIdx.y * 32;
    int b = bc >> 4, c = bc & 15;
    __shared__ float sr[258][17], si[258][17];
    __shared__ float2 tw[192];
    int tid = threadIdx.x;
    int w = tid >> 5, l = tid & 31;

    if (tid < 192) {
        float sv, cv;
        __sincosf(-6.28318530717958647692f * (float)tid * (1.f / 256.f), &sv, &cv);
        tw[tid] = make_float2(cv, sv);
    }
    for (int i = tid; i < 8192; i += 512) {
        int f = i >> 5, tt = i & 31;
        float v = x[((size_t)bc * 256 + f) * 512 + t0 + tt];
        if (tt & 1) si[f][tt >> 1] = v; else sr[f][tt >> 1] = v;
    }
    __syncthreads();

    #pragma unroll
    for (int stage = 0; stage < 4; ++stage) {
        int ms = 6 - 2 * stage;
        int m = 1 << ms;
        #pragma unroll
        for (int half = 0; half < 2; ++half) {
            int bfy = l + 32 * half;
            int g = bfy >> ms, p = bfy & (m - 1);
            int base = (g << (ms + 2)) + p;
            int e1 = p << (2 * stage);
            float2 w1 = tw[e1], w2 = tw[2 * e1], w3 = tw[3 * e1];
            float ar = sr[base][w],        ai = si[base][w];
            float br = sr[base + m][w],    bi = si[base + m][w];
            float cr = sr[base + 2*m][w],  ci = si[base + 2*m][w];
            float dr = sr[base + 3*m][w],  di = si[base + 3*m][w];
            float t0r = ar + cr, t0i = ai + ci;
            float t1r = ar - cr, t1i = ai - ci;
            float t2r = br + dr, t2i = bi + di;
            float t3r = br - dr, t3i = bi - di;
            sr[base][w] = t0r + t2r;  si[base][w] = t0i + t2i;
            float u1r = t1r + t3i, u1i = t1i - t3r;
            sr[base + m][w]   = u1r * w1.x - u1i * w1.y;
            si[base + m][w]   = u1r * w1.y + u1i * w1.x;
            float v2r = t0r - t2r, v2i = t0i - t2i;
            sr[base + 2*m][w] = v2r * w2.x - v2i * w2.y;
            si[base + 2*m][w] = v2r * w2.y + v2i * w2.x;
            float u3r = t1r - t3i, u3i = t1i + t3r;
            sr[base + 3*m][w] = u3r * w3.x - u3i * w3.y;
            si[base + 3*m][w] = u3r * w3.y + u3i * w3.x;
        }
        __syncwarp();
    }

    float va[5][4];
    #pragma unroll
    for (int r = 0; r < 4; ++r) {
        int k = l + 32 * r;
        int ik = dr4(k), im = dr4((256 - k) & 255);
        float zkr = sr[ik][w], zki = si[ik][w];
        float zmr = sr[im][w], zmi = si[im][w];
        va[r][0] = 0.5f * (zkr + zmr);
        va[r][1] = 0.5f * (zki - zmi);
        va[r][2] = 0.5f * (zki + zmi);
        va[r][3] = 0.5f * (zmr - zkr);
    }
    if (l == 0) {
        int ik = dr4(128);
        float zkr = sr[ik][w], zki = si[ik][w];
        va[4][0] = zkr; va[4][1] = 0.f;
        va[4][2] = zki; va[4][3] = 0.f;
    }
    __syncwarp();
    #pragma unroll
    for (int r = 0; r < 4; ++r) {
        int k = l + 32 * r;
        sr[k][w] = va[r][0];        si[k][w] = va[r][1];
        sr[129 + k][w] = va[r][2];  si[129 + k][w] = va[r][3];
    }
    if (l == 0) {
        sr[128][w] = va[4][0];       si[128][w] = va[4][1];
        sr[129 + 128][w] = va[4][2]; si[129 + 128][w] = va[4][3];
    }
    __syncthreads();

    for (int i = tid; i < 4128; i += 512) {
        int k = i >> 5, tt = i & 31;
        int j = tt >> 1;
        int row = (tt & 1) ? (129 + k) : k;
        g_zraw[(((size_t)b * 32 + c)      * 129 + k) * 512 + t0 + tt] = sr[row][j];
        g_zraw[(((size_t)b * 32 + 16 + c) * 129 + k) * 512 + t0 + tt] = si[row][j];
    }
}

// ---------------- K2a: partial stats, grid (8,16,6), block 512 --------------
__global__ void k_stats1() {
    __shared__ float s_sum[16][32], s_sq[16][32];
    int w = threadIdx.x >> 5, l = threadIdx.x & 31;
    int b = blockIdx.x;
    int t = blockIdx.y * 32 + l;
    int part = blockIdx.z;
    const float* base = g_zraw + (size_t)b * 4128 * 512 + t;
    float sum = 0.f, sq = 0.f;
    int e0 = part * 688 + w * 43;
    #pragma unroll 4
    for (int e = e0; e < e0 + 43; ++e) {
        float v = base[(size_t)e * 512];
        sum += v; sq = fmaf(v, v, sq);
    }
    s_sum[w][l] = sum; s_sq[w][l] = sq;
    __syncthreads();
    if (threadIdx.x < 32) {
        int n = b * 512 + blockIdx.y * 32 + threadIdx.x;
        float S = 0.f, Q = 0.f;
        #pragma unroll
        for (int i = 0; i < 16; ++i) { S += s_sum[i][threadIdx.x]; Q += s_sq[i][threadIdx.x]; }
        g_psum[n * 6 + part] = S;
        g_psq [n * 6 + part] = Q;
    }
}

// ---------------- K2b: finalize stats ---------------------------------------
__global__ void k_stats2() {
    int n = blockIdx.x * 256 + threadIdx.x;
    float S = 0.f, Q = 0.f;
    #pragma unroll
    for (int p = 0; p < 6; ++p) { S += g_psum[n * 6 + p]; Q += g_psq[n * 6 + p]; }
    float mean = S * (1.f / 4128.f);
    float var = (Q - S * mean) * (1.f / 4127.f);
    g_mean[n] = mean;
    g_rstd[n] = __fdividef(1.f, sqrtf(fmaxf(var, 0.f)) + 1e-8f);
}

// ---------------- K3: normalize + input-gate GEMM (R3 config, 4 blocks/SM) --
// grid (129, 64), block 256. Pair-interleaved gate output layout.
__global__ void __launch_bounds__(256, 4) k_gates(
    const float* __restrict__ nw, const float* __restrict__ nb,
    const float* __restrict__ wihf, const float* __restrict__ bihf, const float* __restrict__ bhhf,
    const float* __restrict__ wihb, const float* __restrict__ bihb, const float* __restrict__ bhhb) {
    int k = blockIdx.x;
    int n0 = blockIdx.y * 64;
    int b = n0 >> 9, tl0 = n0 & 511;
    __shared__ __align__(16) float ys[32][68];
    __shared__ __align__(16) union {
        unsigned long long w[32][130];
        float stage[64][132];
    } u;
    __shared__ float nws[32], nbs[32], means[64], rstds[64], bs[128];
    int tid = threadIdx.x;

    for (int i = tid; i < 2048; i += 256) {
        int c2 = i >> 6, tt = i & 63;
        ys[c2][tt] = g_zraw[(((size_t)b * 32 + c2) * 129 + k) * 512 + tl0 + tt];
    }
    for (int i = tid; i < 2048; i += 256) {
        int r = i >> 5, q = i & 31;
        float wf = wihf[i]; u.w[q][r] = pack2(wf, wf);
        float wb = wihb[i]; u.w[q][64 + r] = pack2(wb, wb);
    }
    if (tid < 64) bs[tid] = bihf[tid] + bhhf[tid];
    else if (tid < 128) bs[tid] = bihb[tid - 64] + bhhb[tid - 64];
    if (tid < 32) { nws[tid] = nw[tid * 129 + k]; nbs[tid] = nb[tid * 129 + k]; }
    if (tid >= 32 && tid < 96) { means[tid - 32] = g_mean[n0 + tid - 32]; rstds[tid - 32] = g_rstd[n0 + tid - 32]; }
    __syncthreads();

    for (int i = tid; i < 2048; i += 256) {
        int c2 = i >> 6, tt = i & 63;
        ys[c2][tt] = (ys[c2][tt] - means[tt]) * rstds[tt] * nws[c2] + nbs[c2];
    }
    __syncthreads();

    int gg = tid >> 4, tg = tid & 15;
    int g0 = gg << 3, t4 = tg << 2;
    unsigned long long acc[8][2];
    #pragma unroll
    for (int j = 0; j < 8; ++j) {
        float bj = bs[g0 + j];
        acc[j][0] = pack2(bj, bj);
        acc[j][1] = acc[j][0];
    }
    #pragma unroll 4
    for (int q = 0; q < 32; ++q) {
        ulonglong2 y2 = *reinterpret_cast<const ulonglong2*>(&ys[q][t4]);
        const ulonglong2* wp = reinterpret_cast<const ulonglong2*>(&u.w[q][g0]);
        ulonglong2 w01 = wp[0], w23 = wp[1], w45 = wp[2], w67 = wp[3];
        acc[0][0] = ffma2(y2.x, w01.x, acc[0][0]);  acc[0][1] = ffma2(y2.y, w01.x, acc[0][1]);
        acc[1][0] = ffma2(y2.x, w01.y, acc[1][0]);  acc[1][1] = ffma2(y2.y, w01.y, acc[1][1]);
        acc[2][0] = ffma2(y2.x, w23.x, acc[2][0]);  acc[2][1] = ffma2(y2.y, w23.x, acc[2][1]);
        acc[3][0] = ffma2(y2.x, w23.y, acc[3][0]);  acc[3][1] = ffma2(y2.y, w23.y, acc[3][1]);
        acc[4][0] = ffma2(y2.x, w45.x, acc[4][0]);  acc[4][1] = ffma2(y2.y, w45.x, acc[4][1]);
        acc[5][0] = ffma2(y2.x, w45.y, acc[5][0]);  acc[5][1] = ffma2(y2.y, w45.y, acc[5][1]);
        acc[6][0] = ffma2(y2.x, w67.x, acc[6][0]);  acc[6][1] = ffma2(y2.y, w67.x, acc[6][1]);
        acc[7][0] = ffma2(y2.x, w67.y, acc[7][0]);  acc[7][1] = ffma2(y2.y, w67.y, acc[7][1]);
    }
    __syncthreads();

    // stage with pair-interleaved gate positions: row r (0..63 within dir)
    // -> pos dir*64 + 2*(r&31) + (r>>5), so lstm lane j loads float2 at 2j.
    #pragma unroll
    for (int j = 0; j < 8; ++j) {
        int g = g0 + j;
        int dir = g >> 6, r = g & 63;
        int pos = (dir << 6) + ((r & 31) << 1) + (r >> 5);
        float v00, v01, v10, v11;
        unpack2(acc[j][0], v00, v01);
        unpack2(acc[j][1], v10, v11);
        u.stage[t4 + 0][pos] = v00;
        u.stage[t4 + 1][pos] = v01;
        u.stage[t4 + 2][pos] = v10;
        u.stage[t4 + 3][pos] = v11;
    }
    __syncthreads();

    for (int i = tid; i < 2048; i += 256) {
        int tt = i >> 5, g4 = (i & 31) << 2;
        float4 v = *reinterpret_cast<const float4*>(&u.stage[tt][g4]);
        *reinterpret_cast<float4*>(&g_pre[((size_t)(n0 + tt) * 129 + k) * 128 + g4]) = v;
    }
}

// ---------------- K4: recurrent-only LSTM, one warp per (seq, dir) ----------
__global__ void __launch_bounds__(256) k_lstm(
    const float* __restrict__ whhf, const float* __restrict__ whhb) {
    int wg = blockIdx.x * 8 + (threadIdx.x >> 5);
    int lane = threadIdx.x & 31;
    int n = wg >> 1, dir = wg & 1;

    const float* whh = dir ? whhb : whhf;
    float wh0[16], wh1[16];
    #pragma unroll
    for (int q = 0; q < 16; ++q) {
        wh0[q] = whh[lane * 16 + q];
        wh1[q] = whh[(lane + 32) * 16 + q];
    }

    const float* pbase = g_pre + (size_t)n * 129 * 128 + dir * 64;
    float* hbase = g_h + (size_t)n * 129 * 32 + dir * 16;

    float h = 0.f, cst = 0.f;
    int k = dir ? 128 : 0;
    int stepd = dir ? -1 : 1;
    float2 p = *reinterpret_cast<const float2*>(&pbase[k * 128 + 2 * lane]);

    for (int s = 0; s < 129; ++s) {
        int kn = k + stepd;
        float2 np = make_float2(0.f, 0.f);
        if (s < 128) {
            np = *reinterpret_cast<const float2*>(&pbase[kn * 128 + 2 * lane]);
        }
        float a0 = p.x, a1 = p.y, c0 = 0.f, c1 = 0.f;
        #pragma unroll
        for (int q = 0; q < 8; ++q) {
            float hv = __shfl_sync(0xffffffffu, h, q);
            a0 = fmaf(hv, wh0[q], a0);
            a1 = fmaf(hv, wh1[q], a1);
        }
        #pragma unroll
        for (int q = 8; q < 16; ++q) {
            float hv = __shfl_sync(0xffffffffu, h, q);
            c0 = fmaf(hv, wh0[q], c0);
            c1 = fmaf(hv, wh1[q], c1);
        }
        a0 += c0; a1 += c1;
        float fo0 = __shfl_xor_sync(0xffffffffu, a0, 16);
        float fo1 = __shfl_xor_sync(0xffffffffu, a1, 16);
        if (lane < 16) {
            float ig = sigf(a0);
            float gg = tanhfast(a1);
            float ff = sigf(fo0);
            float oo = sigf(fo1);
            cst = fmaf(ff, cst, ig * gg);
            h = oo * tanhfast(cst);
            hbase[k * 32 + lane] = h;
        }
        p = np; k = kn;
    }
}

// ---------------- K5: linear(2H->2C) + complex multiply ---------------------
__global__ void k_lin_cmul(const float* __restrict__ lw, const float* __restrict__ lb) {
    int k = blockIdx.x, t0 = blockIdx.y * 32, b = blockIdx.z;
    __shared__ float hs[32][33];    // [t][j]
    __shared__ float lws[32][32];   // [c2][j]
    __shared__ float lbs[32];
    __shared__ float yls[32][33];   // [c2][t]
    int tid = threadIdx.x;

    for (int i = tid; i < 1024; i += 256) lws[i >> 5][i & 31] = lw[i];
    if (tid < 32) lbs[tid] = lb[tid];
    for (int i = tid; i < 1024; i += 256) {
        int tt = i >> 5, j = i & 31;
        hs[tt][j] = g_h[(((size_t)(b * 512 + t0 + tt)) * 129 + k) * 32 + j];
    }
    __syncthreads();

    int tt = tid & 31, g = tid >> 5;
    #pragma unroll
    for (int ci = 0; ci < 4; ++ci) {
        int c2 = g + ci * 8;
        float acc = lbs[c2];
        #pragma unroll
        for (int j = 0; j < 32; ++j) acc = fmaf(hs[tt][j], lws[c2][j], acc);
        yls[c2][tt] = acc;
    }
    __syncthreads();

    size_t basez = ((size_t)(b * 32) * 129 + k) * 512 + t0 + tt;
    const size_t ps = (size_t)129 * 512;
    #pragma unroll
    for (int ci = 0; ci < 4; ++ci) {
        int c2 = g + ci * 8;
        if (c2 < 16) {
            float xr = g_zraw[basez + (size_t)c2 * ps];
            float xi = g_zraw[basez + (size_t)(c2 + 16) * ps];
            float yr = yls[c2][tt], yi = yls[c2 + 16][tt];
            g_P[basez + (size_t)c2 * ps] = yr * xr - yi * xi;
        } else {
            int c = c2 - 16;
            float xr = g_zraw[basez + (size_t)c * ps];
            float xi = g_zraw[basez + (size_t)c2 * ps];
            float yr = yls[c][tt], yi = yls[c2][tt];
            g_P[basez + (size_t)c2 * ps] = yr * xi + yi * xr;
        }
    }
}

// ---------------- K6: irfft, warp-private radix-4, spectrum-pair packed -----
// grid (128, 16), block 512.
__global__ void __launch_bounds__(512) k_fft_inv(float* __restrict__ out) {
    int bc = blockIdx.x;
    int t0 = blockIdx.y * 32;
    int b = bc >> 4, c = bc & 15;
    __shared__ float sr[258][17], si[258][17];
    __shared__ float2 tw[192];
    int tid = threadIdx.x;
    int w = tid >> 5, l = tid & 31;

    if (tid < 192) {
        float sv, cv;
        __sincosf(6.28318530717958647692f * (float)tid * (1.f / 256.f), &sv, &cv);
        tw[tid] = make_float2(cv, sv);
    }
    for (int i = tid; i < 4128; i += 512) {
        int k = i >> 5, tt = i & 31;
        int j = tt >> 1;
        int row = (tt & 1) ? (129 + k) : k;
        sr[row][j] = g_P[(((size_t)b * 32 + c)      * 129 + k) * 512 + t0 + tt];
        si[row][j] = g_P[(((size_t)b * 32 + 16 + c) * 129 + k) * 512 + t0 + tt];
    }
    __syncthreads();

    float vz[8][2];
    #pragma unroll
    for (int r = 0; r < 8; ++r) {
        int row = l + 32 * r;
        float zr, zi;
        if (row <= 128) {
            float par = sr[row][w];
            float pai = (row == 0 || row == 128) ? 0.f : si[row][w];
            float pbr = sr[129 + row][w];
            float pbi = (row == 0 || row == 128) ? 0.f : si[129 + row][w];
            zr = par - pbi; zi = pai + pbr;
        } else {
            int m = 256 - row;
            float par = sr[m][w], pai = si[m][w];
            float pbr = sr[129 + m][w], pbi = si[129 + m][w];
            zr = par + pbi; zi = pbr - pai;
        }
        vz[r][0] = zr; vz[r][1] = zi;
    }
    __syncwarp();
    #pragma unroll
    for (int r = 0; r < 8; ++r) {
        int row = l + 32 * r;
        sr[row][w] = vz[r][0];
        si[row][w] = vz[r][1];
    }
    __syncwarp();

    #pragma unroll
    for (int stage = 0; stage < 4; ++stage) {
        int ms = 6 - 2 * stage;
        int m = 1 << ms;
        #pragma unroll
        for (int half = 0; half < 2; ++half) {
            int bfy = l + 32 * half;
            int g = bfy >> ms, p = bfy & (m - 1);
            int base = (g << (ms + 2)) + p;
            int e1 = p << (2 * stage);
            float2 w1 = tw[e1], w2 = tw[2 * e1], w3 = tw[3 * e1];
            float ar = sr[base][w],        ai = si[base][w];
            float br = sr[base + m][w],    bi = si[base + m][w];
            float cr = sr[base + 2*m][w],  ci = si[base + 2*m][w];
            float dr = sr[base + 3*m][w],  di = si[base + 3*m][w];
            float t0r = ar + cr, t0i = ai + ci;
            float t1r = ar - cr, t1i = ai - ci;
            float t2r = br + dr, t2i = bi + di;
            float t3r = br - dr, t3i = bi - di;
            sr[base][w] = t0r + t2r;  si[base][w] = t0i + t2i;
            float u1r = t1r - t3i, u1i = t1i + t3r;
            sr[base + m][w]   = u1r * w1.x - u1i * w1.y;
            si[base + m][w]   = u1r * w1.y + u1i * w1.x;
            float v2r = t0r - t2r, v2i = t0i - t2i;
            sr[base + 2*m][w] = v2r * w2.x - v2i * w2.y;
            si[base + 2*m][w] = v2r * w2.y + v2i * w2.x;
            float u3r = t1r + t3i, u3i = t1i - t3r;
            sr[base + 3*m][w] = u3r * w3.x - u3i * w3.y;
            si[base + 3*m][w] = u3r * w3.y + u3i * w3.x;
        }
        __syncwarp();
    }
    __syncthreads();

    const float inv = 1.f / 256.f;
    for (int i = tid; i < 8192; i += 512) {
        int f = i >> 5, tt = i & 31;
        int j = tt >> 1;
        int src = dr4(f);
        float v = (tt & 1) ? si[src][j] : sr[src][j];
        out[((size_t)bc * 256 + f) * 512 + t0 + tt] = v * inv;
    }
}

// ---------------- launcher ---------------------------------------------------
extern "C" void kernel_launch(void* const* d_in, const int* in_sizes, int n_in,
                              void* d_out, int out_size) {
    const float* x    = (const float*)d_in[0];
    const float* nw   = (const float*)d_in[1];
    const float* nb   = (const float*)d_in[2];
    const float* wihf = (const float*)d_in[3];
    const float* whhf = (const float*)d_in[4];
    const float* bihf = (const float*)d_in[5];
    const float* bhhf = (const float*)d_in[6];
    const float* wihb = (const float*)d_in[7];
    const float* whhb = (const float*)d_in[8];
    const float* bihb = (const float*)d_in[9];
    const float* bhhb = (const float*)d_in[10];
    const float* lw   = (const float*)d_in[11];
    const float* lb   = (const float*)d_in[12];
    float* out = (float*)d_out;

    k_fft_fwd<<<dim3(128, 16), 512>>>(x);
    k_stats1<<<dim3(8, 16, 6), 512>>>();
    k_stats2<<<16, 256>>>();
    k_gates<<<dim3(129, 64), 256>>>(nw, nb, wihf, bihf, bhhf, wihb, bihb, bhhb);
    k_lstm<<<1024, 256>>>(whhf, whhb);
    k_lin_cmul<<<dim3(129, 16, 8), 256>>>(lw, lb);
    k_fft_inv<<<dim3(128, 16), 512>>>(out);
}

// round 11
// speedup vs baseline: 1.2002x; 1.1887x over previous
#include <cuda_runtime.h>
#include <cstdint>

#define BB 8
#define CC 16
#define FDIM 256
#define F2 129
#define TT 512
#define C2 32
#define HH 16
#define NT (BB*TT)

// ---------------- device scratch ----------------
__device__ float g_zraw[(size_t)BB*C2*F2*TT];   // spectrum planes (b, c2, k, t): re c=0..15, im c=16..31
__device__ float g_pre [(size_t)NT*F2*128];     // gate preactivations (n, k, 128): [dir*64 + row]
__device__ float g_h   [(size_t)NT*F2*C2];      // LSTM hidden cat(fwd,bwd): (n, k, 2H)
__device__ float g_P   [(size_t)BB*C2*F2*TT];   // product spectrum planes
__device__ float g_mean[NT];
__device__ float g_rstd[NT];
__device__ float g_psum[NT*6];
__device__ float g_psq [NT*6];

__device__ __forceinline__ float sigf(float x) {
    return __fdividef(1.f, 1.f + __expf(-x));
}
__device__ __forceinline__ float tanhfast(float x) {
    return fmaf(2.f, __fdividef(1.f, 1.f + __expf(-2.f * x)), -1.f);
}
__device__ __forceinline__ unsigned int f2tf32(float f) {
    unsigned int r;
    asm("cvt.rna.tf32.f32 %0, %1;" : "=r"(r) : "f"(f));
    return r;
}
__device__ __forceinline__ void mma_tf32(float* d,
    unsigned int a0, unsigned int a1, unsigned int a2, unsigned int a3,
    unsigned int b0, unsigned int b1) {
    asm volatile(
        "mma.sync.aligned.m16n8k8.row.col.f32.tf32.tf32.f32 "
        "{%0,%1,%2,%3}, {%4,%5,%6,%7}, {%8,%9}, {%0,%1,%2,%3};"
        : "+f"(d[0]), "+f"(d[1]), "+f"(d[2]), "+f"(d[3])
        : "r"(a0), "r"(a1), "r"(a2), "r"(a3), "r"(b0), "r"(b1));
}
__device__ __forceinline__ int dr4(int k) {   // base-4 digit reversal, 4 digits
    return ((k & 3) << 6) | (((k >> 2) & 3) << 4) | (((k >> 4) & 3) << 2) | ((k >> 6) & 3);
}

// ---------------- K1: forward rfft, warp-private radix-4, real-pair packed --
// grid (128, 16), block 512 (16 warps). 32 t-cols -> 16 complex FFTs, one/warp.
__global__ void __launch_bounds__(512) k_fft_fwd(const float* __restrict__ x) {
    int bc = blockIdx.x;
    int t0 = blockIdx.y * 32;
    int b = bc >> 4, c = bc & 15;
    __shared__ float sr[258][17], si[258][17];
    __shared__ float2 tw[192];
    int tid = threadIdx.x;
    int w = tid >> 5, l = tid & 31;

    if (tid < 192) {
        float sv, cv;
        __sincosf(-6.28318530717958647692f * (float)tid * (1.f / 256.f), &sv, &cv);
        tw[tid] = make_float2(cv, sv);
    }
    for (int i = tid; i < 8192; i += 512) {
        int f = i >> 5, tt = i & 31;
        float v = x[((size_t)bc * 256 + f) * 512 + t0 + tt];
        if (tt & 1) si[f][tt >> 1] = v; else sr[f][tt >> 1] = v;
    }
    __syncthreads();

    #pragma unroll
    for (int stage = 0; stage < 4; ++stage) {
        int ms = 6 - 2 * stage;
        int m = 1 << ms;
        #pragma unroll
        for (int half = 0; half < 2; ++half) {
            int bfy = l + 32 * half;
            int g = bfy >> ms, p = bfy & (m - 1);
            int base = (g << (ms + 2)) + p;
            int e1 = p << (2 * stage);
            float2 w1 = tw[e1], w2 = tw[2 * e1], w3 = tw[3 * e1];
            float ar = sr[base][w],        ai = si[base][w];
            float br = sr[base + m][w],    bi = si[base + m][w];
            float cr = sr[base + 2*m][w],  ci = si[base + 2*m][w];
            float dr = sr[base + 3*m][w],  di = si[base + 3*m][w];
            float t0r = ar + cr, t0i = ai + ci;
            float t1r = ar - cr, t1i = ai - ci;
            float t2r = br + dr, t2i = bi + di;
            float t3r = br - dr, t3i = bi - di;
            sr[base][w] = t0r + t2r;  si[base][w] = t0i + t2i;
            float u1r = t1r + t3i, u1i = t1i - t3r;
            sr[base + m][w]   = u1r * w1.x - u1i * w1.y;
            si[base + m][w]   = u1r * w1.y + u1i * w1.x;
            float v2r = t0r - t2r, v2i = t0i - t2i;
            sr[base + 2*m][w] = v2r * w2.x - v2i * w2.y;
            si[base + 2*m][w] = v2r * w2.y + v2i * w2.x;
            float u3r = t1r - t3i, u3i = t1i + t3r;
            sr[base + 3*m][w] = u3r * w3.x - u3i * w3.y;
            si[base + 3*m][w] = u3r * w3.y + u3i * w3.x;
        }
        __syncwarp();
    }

    float va[5][4];
    #pragma unroll
    for (int r = 0; r < 4; ++r) {
        int k = l + 32 * r;
        int ik = dr4(k), im = dr4((256 - k) & 255);
        float zkr = sr[ik][w], zki = si[ik][w];
        float zmr = sr[im][w], zmi = si[im][w];
        va[r][0] = 0.5f * (zkr + zmr);
        va[r][1] = 0.5f * (zki - zmi);
        va[r][2] = 0.5f * (zki + zmi);
        va[r][3] = 0.5f * (zmr - zkr);
    }
    if (l == 0) {
        int ik = dr4(128);
        float zkr = sr[ik][w], zki = si[ik][w];
        va[4][0] = zkr; va[4][1] = 0.f;
        va[4][2] = zki; va[4][3] = 0.f;
    }
    __syncwarp();
    #pragma unroll
    for (int r = 0; r < 4; ++r) {
        int k = l + 32 * r;
        sr[k][w] = va[r][0];        si[k][w] = va[r][1];
        sr[129 + k][w] = va[r][2];  si[129 + k][w] = va[r][3];
    }
    if (l == 0) {
        sr[128][w] = va[4][0];       si[128][w] = va[4][1];
        sr[129 + 128][w] = va[4][2]; si[129 + 128][w] = va[4][3];
    }
    __syncthreads();

    for (int i = tid; i < 4128; i += 512) {
        int k = i >> 5, tt = i & 31;
        int j = tt >> 1;
        int row = (tt & 1) ? (129 + k) : k;
        g_zraw[(((size_t)b * 32 + c)      * 129 + k) * 512 + t0 + tt] = sr[row][j];
        g_zraw[(((size_t)b * 32 + 16 + c) * 129 + k) * 512 + t0 + tt] = si[row][j];
    }
}

// ---------------- K2a: partial stats, grid (8,16,6), block 512 --------------
__global__ void k_stats1() {
    __shared__ float s_sum[16][32], s_sq[16][32];
    int w = threadIdx.x >> 5, l = threadIdx.x & 31;
    int b = blockIdx.x;
    int t = blockIdx.y * 32 + l;
    int part = blockIdx.z;
    const float* base = g_zraw + (size_t)b * 4128 * 512 + t;
    float sum = 0.f, sq = 0.f;
    int e0 = part * 688 + w * 43;
    #pragma unroll 4
    for (int e = e0; e < e0 + 43; ++e) {
        float v = base[(size_t)e * 512];
        sum += v; sq = fmaf(v, v, sq);
    }
    s_sum[w][l] = sum; s_sq[w][l] = sq;
    __syncthreads();
    if (threadIdx.x < 32) {
        int n = b * 512 + blockIdx.y * 32 + threadIdx.x;
        float S = 0.f, Q = 0.f;
        #pragma unroll
        for (int i = 0; i < 16; ++i) { S += s_sum[i][threadIdx.x]; Q += s_sq[i][threadIdx.x]; }
        g_psum[n * 6 + part] = S;
        g_psq [n * 6 + part] = Q;
    }
}

// ---------------- K2b: finalize stats ---------------------------------------
__global__ void k_stats2() {
    int n = blockIdx.x * 256 + threadIdx.x;
    float S = 0.f, Q = 0.f;
    #pragma unroll
    for (int p = 0; p < 6; ++p) { S += g_psum[n * 6 + p]; Q += g_psq[n * 6 + p]; }
    float mean = S * (1.f / 4128.f);
    float var = (Q - S * mean) * (1.f / 4127.f);
    g_mean[n] = mean;
    g_rstd[n] = __fdividef(1.f, sqrtf(fmaxf(var, 0.f)) + 1e-8f);
}

// ---------------- K3: normalize + input-gate GEMM via tf32 mma.sync ---------
// grid (129, 64), block 256 (8 warps). Block: one k, 64 t (M), 128 gates (N), K=32.
// Warp w: m-tile (w&3)*16, n-half (w>>2)*64 covered by 8 n8 tiles.
__global__ void __launch_bounds__(256) k_gates(
    const float* __restrict__ nw, const float* __restrict__ nb,
    const float* __restrict__ wihf, const float* __restrict__ bihf, const float* __restrict__ bhhf,
    const float* __restrict__ wihb, const float* __restrict__ bihb, const float* __restrict__ bhhb) {
    int k = blockIdx.x;
    int n0 = blockIdx.y * 64;
    int b = n0 >> 9, tl0 = n0 & 511;
    __shared__ float ys[32][72];     // [q][t], pitch 72 (conflict-free A frags)
    __shared__ float ws[128][36];    // [gate][q], pitch 36 (conflict-free B frags)
    __shared__ float nws[32], nbs[32], means[64], rstds[64], bs[128];
    int tid = threadIdx.x;

    for (int i = tid; i < 2048; i += 256) {
        int c2 = i >> 6, tt = i & 63;
        ys[c2][tt] = g_zraw[(((size_t)b * 32 + c2) * 129 + k) * 512 + tl0 + tt];
    }
    for (int i = tid; i < 4096; i += 256) {
        int g = i >> 5, q = i & 31;
        ws[g][q] = (g < 64) ? wihf[g * 32 + q] : wihb[(g - 64) * 32 + q];
    }
    if (tid < 64) bs[tid] = bihf[tid] + bhhf[tid];
    else if (tid < 128) bs[tid] = bihb[tid - 64] + bhhb[tid - 64];
    if (tid < 32) { nws[tid] = nw[tid * 129 + k]; nbs[tid] = nb[tid * 129 + k]; }
    if (tid >= 128 && tid < 192) { means[tid - 128] = g_mean[n0 + tid - 128]; rstds[tid - 128] = g_rstd[n0 + tid - 128]; }
    __syncthreads();

    for (int i = tid; i < 2048; i += 256) {
        int c2 = i >> 6, tt = i & 63;
        ys[c2][tt] = (ys[c2][tt] - means[tt]) * rstds[tt] * nws[c2] + nbs[c2];
    }
    __syncthreads();

    int wid = tid >> 5, lane = tid & 31;
    int gid = lane >> 2, tid4 = lane & 3;
    int m_base = (wid & 3) << 4;          // 0,16,32,48
    int n_base0 = (wid >> 2) << 6;        // 0 or 64

    float acc[8][4];
    #pragma unroll
    for (int j = 0; j < 8; ++j) {
        int gb = n_base0 + j * 8 + tid4 * 2;
        acc[j][0] = bs[gb];     acc[j][1] = bs[gb + 1];
        acc[j][2] = bs[gb];     acc[j][3] = bs[gb + 1];
    }

    #pragma unroll
    for (int ks = 0; ks < 32; ks += 8) {
        // PTX m16n8k8 tf32 A fragment:
        //   a0 = A(g,    t)    a1 = A(g+8, t)
        //   a2 = A(g,    t+4)  a3 = A(g+8, t+4)
        unsigned int a0 = f2tf32(ys[ks + tid4    ][m_base + gid]);
        unsigned int a1 = f2tf32(ys[ks + tid4    ][m_base + gid + 8]);
        unsigned int a2 = f2tf32(ys[ks + tid4 + 4][m_base + gid]);
        unsigned int a3 = f2tf32(ys[ks + tid4 + 4][m_base + gid + 8]);
        #pragma unroll
        for (int j = 0; j < 8; ++j) {
            int gb = n_base0 + j * 8 + gid;
            // B (col-major K x N): b0 = B(t, g), b1 = B(t+4, g)
            unsigned int b0 = f2tf32(ws[gb][ks + tid4]);
            unsigned int b1 = f2tf32(ws[gb][ks + tid4 + 4]);
            mma_tf32(acc[j], a0, a1, a2, a3, b0, b1);
        }
    }

    // store: thread owns D rows (gid, gid+8), gate cols tid4*2, tid4*2+1 per tile
    #pragma unroll
    for (int j = 0; j < 8; ++j) {
        int gate = n_base0 + j * 8 + tid4 * 2;
        int trow = n0 + m_base + gid;
        float2 v0 = make_float2(acc[j][0], acc[j][1]);
        float2 v1 = make_float2(acc[j][2], acc[j][3]);
        *reinterpret_cast<float2*>(&g_pre[((size_t)trow * 129 + k) * 128 + gate]) = v0;
        *reinterpret_cast<float2*>(&g_pre[((size_t)(trow + 8) * 129 + k) * 128 + gate]) = v1;
    }
}

// ---------------- K4: recurrent-only LSTM, one warp per (seq, dir) ----------
__global__ void __launch_bounds__(256) k_lstm(
    const float* __restrict__ whhf, const float* __restrict__ whhb) {
    int wg = blockIdx.x * 8 + (threadIdx.x >> 5);
    int lane = threadIdx.x & 31;
    int n = wg >> 1, dir = wg & 1;

    const float* whh = dir ? whhb : whhf;
    float wh0[16], wh1[16];
    #pragma unroll
    for (int q = 0; q < 16; ++q) {
        wh0[q] = whh[lane * 16 + q];
        wh1[q] = whh[(lane + 32) * 16 + q];
    }

    const float* pbase = g_pre + (size_t)n * 129 * 128 + dir * 64;
    float* hbase = g_h + (size_t)n * 129 * 32 + dir * 16;

    float h = 0.f, cst = 0.f;
    int k = dir ? 128 : 0;
    int stepd = dir ? -1 : 1;
    float p0 = pbase[k * 128 + lane];
    float p1 = pbase[k * 128 + 32 + lane];

    for (int s = 0; s < 129; ++s) {
        int kn = k + stepd;
        float np0 = 0.f, np1 = 0.f;
        if (s < 128) {
            np0 = pbase[kn * 128 + lane];
            np1 = pbase[kn * 128 + 32 + lane];
        }
        float a0 = p0, a1 = p1, c0 = 0.f, c1 = 0.f;
        #pragma unroll
        for (int q = 0; q < 8; ++q) {
            float hv = __shfl_sync(0xffffffffu, h, q);
            a0 = fmaf(hv, wh0[q], a0);
            a1 = fmaf(hv, wh1[q], a1);
        }
        #pragma unroll
        for (int q = 8; q < 16; ++q) {
            float hv = __shfl_sync(0xffffffffu, h, q);
            c0 = fmaf(hv, wh0[q], c0);
            c1 = fmaf(hv, wh1[q], c1);
        }
        a0 += c0; a1 += c1;
        float fo0 = __shfl_xor_sync(0xffffffffu, a0, 16);
        float fo1 = __shfl_xor_sync(0xffffffffu, a1, 16);
        if (lane < 16) {
            float ig = sigf(a0);
            float gg = tanhfast(a1);
            float ff = sigf(fo0);
            float oo = sigf(fo1);
            cst = fmaf(ff, cst, ig * gg);
            h = oo * tanhfast(cst);
            hbase[k * 32 + lane] = h;
        }
        p0 = np0; p1 = np1; k = kn;
    }
}

// ---------------- K5: linear(2H->2C) + complex multiply ---------------------
__global__ void k_lin_cmul(const float* __restrict__ lw, const float* __restrict__ lb) {
    int k = blockIdx.x, t0 = blockIdx.y * 32, b = blockIdx.z;
    __shared__ float hs[32][33];    // [t][j]
    __shared__ float lws[32][32];   // [c2][j]
    __shared__ float lbs[32];
    __shared__ float yls[32][33];   // [c2][t]
    int tid = threadIdx.x;

    for (int i = tid; i < 1024; i += 256) lws[i >> 5][i & 31] = lw[i];
    if (tid < 32) lbs[tid] = lb[tid];
    for (int i = tid; i < 1024; i += 256) {
        int tt = i >> 5, j = i & 31;
        hs[tt][j] = g_h[(((size_t)(b * 512 + t0 + tt)) * 129 + k) * 32 + j];
    }
    __syncthreads();

    int tt = tid & 31, g = tid >> 5;
    #pragma unroll
    for (int ci = 0; ci < 4; ++ci) {
        int c2 = g + ci * 8;
        float acc = lbs[c2];
        #pragma unroll
        for (int j = 0; j < 32; ++j) acc = fmaf(hs[tt][j], lws[c2][j], acc);
        yls[c2][tt] = acc;
    }
    __syncthreads();

    size_t basez = ((size_t)(b * 32) * 129 + k) * 512 + t0 + tt;
    const size_t ps = (size_t)129 * 512;
    #pragma unroll
    for (int ci = 0; ci < 4; ++ci) {
        int c2 = g + ci * 8;
        if (c2 < 16) {
            float xr = g_zraw[basez + (size_t)c2 * ps];
            float xi = g_zraw[basez + (size_t)(c2 + 16) * ps];
            float yr = yls[c2][tt], yi = yls[c2 + 16][tt];
            g_P[basez + (size_t)c2 * ps] = yr * xr - yi * xi;
        } else {
            int c = c2 - 16;
            float xr = g_zraw[basez + (size_t)c * ps];
            float xi = g_zraw[basez + (size_t)c2 * ps];
            float yr = yls[c][tt], yi = yls[c2][tt];
            g_P[basez + (size_t)c2 * ps] = yr * xi + yi * xr;
        }
    }
}

// ---------------- K6: irfft, warp-private radix-4, spectrum-pair packed -----
// grid (128, 16), block 512.
__global__ void __launch_bounds__(512) k_fft_inv(float* __restrict__ out) {
    int bc = blockIdx.x;
    int t0 = blockIdx.y * 32;
    int b = bc >> 4, c = bc & 15;
    __shared__ float sr[258][17], si[258][17];
    __shared__ float2 tw[192];
    int tid = threadIdx.x;
    int w = tid >> 5, l = tid & 31;

    if (tid < 192) {
        float sv, cv;
        __sincosf(6.28318530717958647692f * (float)tid * (1.f / 256.f), &sv, &cv);
        tw[tid] = make_float2(cv, sv);
    }
    for (int i = tid; i < 4128; i += 512) {
        int k = i >> 5, tt = i & 31;
        int j = tt >> 1;
        int row = (tt & 1) ? (129 + k) : k;
        sr[row][j] = g_P[(((size_t)b * 32 + c)      * 129 + k) * 512 + t0 + tt];
        si[row][j] = g_P[(((size_t)b * 32 + 16 + c) * 129 + k) * 512 + t0 + tt];
    }
    __syncthreads();

    float vz[8][2];
    #pragma unroll
    for (int r = 0; r < 8; ++r) {
        int row = l + 32 * r;
        float zr, zi;
        if (row <= 128) {
            float par = sr[row][w];
            float pai = (row == 0 || row == 128) ? 0.f : si[row][w];
            float pbr = sr[129 + row][w];
            float pbi = (row == 0 || row == 128) ? 0.f : si[129 + row][w];
            zr = par - pbi; zi = pai + pbr;
        } else {
            int m = 256 - row;
            float par = sr[m][w], pai = si[m][w];
            float pbr = sr[129 + m][w], pbi = si[129 + m][w];
            zr = par + pbi; zi = pbr - pai;
        }
        vz[r][0] = zr; vz[r][1] = zi;
    }
    __syncwarp();
    #pragma unroll
    for (int r = 0; r < 8; ++r) {
        int row = l + 32 * r;
        sr[row][w] = vz[r][0];
        si[row][w] = vz[r][1];
    }
    __syncwarp();

    #pragma unroll
    for (int stage = 0; stage < 4; ++stage) {
        int ms = 6 - 2 * stage;
        int m = 1 << ms;
        #pragma unroll
        for (int half = 0; half < 2; ++half) {
            int bfy = l + 32 * half;
            int g = bfy >> ms, p = bfy & (m - 1);
            int base = (g << (ms + 2)) + p;
            int e1 = p << (2 * stage);
            float2 w1 = tw[e1], w2 = tw[2 * e1], w3 = tw[3 * e1];
            float ar = sr[base][w],        ai = si[base][w];
            float br = sr[base + m][w],    bi = si[base + m][w];
            float cr = sr[base + 2*m][w],  ci = si[base + 2*m][w];
            float dr = sr[base + 3*m][w],  di = si[base + 3*m][w];
            float t0r = ar + cr, t0i = ai + ci;
            float t1r = ar - cr, t1i = ai - ci;
            float t2r = br + dr, t2i = bi + di;
            float t3r = br - dr, t3i = bi - di;
            sr[base][w] = t0r + t2r;  si[base][w] = t0i + t2i;
            float u1r = t1r - t3i, u1i = t1i + t3r;
            sr[base + m][w]   = u1r * w1.x - u1i * w1.y;
            si[base + m][w]   = u1r * w1.y + u1i * w1.x;
            float v2r = t0r - t2r, v2i = t0i - t2i;
            sr[base + 2*m][w] = v2r * w2.x - v2i * w2.y;
            si[base + 2*m][w] = v2r * w2.y + v2i * w2.x;
            float u3r = t1r + t3i, u3i = t1i - t3r;
            sr[base + 3*m][w] = u3r * w3.x - u3i * w3.y;
            si[base + 3*m][w] = u3r * w3.y + u3i * w3.x;
        }
        __syncwarp();
    }
    __syncthreads();

    const float inv = 1.f / 256.f;
    for (int i = tid; i < 8192; i += 512) {
        int f = i >> 5, tt = i & 31;
        int j = tt >> 1;
        int src = dr4(f);
        float v = (tt & 1) ? si[src][j] : sr[src][j];
        out[((size_t)bc * 256 + f) * 512 + t0 + tt] = v * inv;
    }
}

// ---------------- launcher ---------------------------------------------------
extern "C" void kernel_launch(void* const* d_in, const int* in_sizes, int n_in,
                              void* d_out, int out_size) {
    const float* x    = (const float*)d_in[0];
    const float* nw   = (const float*)d_in[1];
    const float* nb   = (const float*)d_in[2];
    const float* wihf = (const float*)d_in[3];
    const float* whhf = (const float*)d_in[4];
    const float* bihf = (const float*)d_in[5];
    const float* bhhf = (const float*)d_in[6];
    const float* wihb = (const float*)d_in[7];
    const float* whhb = (const float*)d_in[8];
    const float* bihb = (const float*)d_in[9];
    const float* bhhb = (const float*)d_in[10];
    const float* lw   = (const float*)d_in[11];
    const float* lb   = (const float*)d_in[12];
    float* out = (float*)d_out;

    k_fft_fwd<<<dim3(128, 16), 512>>>(x);
    k_stats1<<<dim3(8, 16, 6), 512>>>();
    k_stats2<<<16, 256>>>();
    k_gates<<<dim3(129, 64), 256>>>(nw, nb, wihf, bihf, bhhf, wihb, bihb, bhhb);
    k_lstm<<<1024, 256>>>(whhf, whhb);
    k_lin_cmul<<<dim3(129, 16, 8), 256>>>(lw, lb);
    k_fft_inv<<<dim3(128, 16), 512>>>(out);
}

// round 12
// speedup vs baseline: 1.2093x; 1.0076x over previous
#include <cuda_runtime.h>
#include <cstdint>

#define BB 8
#define CC 16
#define FDIM 256
#define F2 129
#define TT 512
#define C2 32
#define HH 16
#define NT (BB*TT)

// ---------------- device scratch ----------------
__device__ float g_zraw[(size_t)BB*C2*F2*TT];   // spectrum planes (b, c2, k, t): re c=0..15, im c=16..31
__device__ float g_pre [(size_t)NT*F2*128];     // gate preactivations (n, k, 128): [dir*64 + row]
__device__ float g_h   [(size_t)NT*F2*C2];      // LSTM hidden cat(fwd,bwd): (n, k, 2H)
__device__ float g_P   [(size_t)BB*C2*F2*TT];   // product spectrum planes
__device__ float g_mean[NT];
__device__ float g_rstd[NT];
__device__ float g_psum[NT*16];                 // 16 channel-partials per n (from fft_fwd)
__device__ float g_psq [NT*16];

__device__ __forceinline__ float sigf(float x) {
    return __fdividef(1.f, 1.f + __expf(-x));
}
__device__ __forceinline__ float tanhfast(float x) {
    return fmaf(2.f, __fdividef(1.f, 1.f + __expf(-2.f * x)), -1.f);
}
__device__ __forceinline__ unsigned int f2tf32(float f) {
    unsigned int r;
    asm("cvt.rna.tf32.f32 %0, %1;" : "=r"(r) : "f"(f));
    return r;
}
__device__ __forceinline__ void mma_tf32(float* d,
    unsigned int a0, unsigned int a1, unsigned int a2, unsigned int a3,
    unsigned int b0, unsigned int b1) {
    asm volatile(
        "mma.sync.aligned.m16n8k8.row.col.f32.tf32.tf32.f32 "
        "{%0,%1,%2,%3}, {%4,%5,%6,%7}, {%8,%9}, {%0,%1,%2,%3};"
        : "+f"(d[0]), "+f"(d[1]), "+f"(d[2]), "+f"(d[3])
        : "r"(a0), "r"(a1), "r"(a2), "r"(a3), "r"(b0), "r"(b1));
}
__device__ __forceinline__ int dr4(int k) {   // base-4 digit reversal, 4 digits
    return ((k & 3) << 6) | (((k >> 2) & 3) << 4) | (((k >> 4) & 3) << 2) | ((k >> 6) & 3);
}

// ---------------- K1: forward rfft + fused norm-stat partials ----------------
// grid (128, 16), block 512 (16 warps). 32 t-cols -> 16 complex FFTs, one/warp.
// Each warp also reduces its (c, c+16) x 129k values into g_psum/g_psq partials.
__global__ void __launch_bounds__(512) k_fft_fwd(const float* __restrict__ x) {
    int bc = blockIdx.x;
    int t0 = blockIdx.y * 32;
    int b = bc >> 4, c = bc & 15;
    __shared__ float sr[258][17], si[258][17];
    __shared__ float2 tw[192];
    int tid = threadIdx.x;
    int w = tid >> 5, l = tid & 31;

    if (tid < 192) {
        float sv, cv;
        __sincosf(-6.28318530717958647692f * (float)tid * (1.f / 256.f), &sv, &cv);
        tw[tid] = make_float2(cv, sv);
    }
    for (int i = tid; i < 8192; i += 512) {
        int f = i >> 5, tt = i & 31;
        float v = x[((size_t)bc * 256 + f) * 512 + t0 + tt];
        if (tt & 1) si[f][tt >> 1] = v; else sr[f][tt >> 1] = v;
    }
    __syncthreads();

    #pragma unroll
    for (int stage = 0; stage < 4; ++stage) {
        int ms = 6 - 2 * stage;
        int m = 1 << ms;
        #pragma unroll
        for (int half = 0; half < 2; ++half) {
            int bfy = l + 32 * half;
            int g = bfy >> ms, p = bfy & (m - 1);
            int base = (g << (ms + 2)) + p;
            int e1 = p << (2 * stage);
            float2 w1 = tw[e1], w2 = tw[2 * e1], w3 = tw[3 * e1];
            float ar = sr[base][w],        ai = si[base][w];
            float br = sr[base + m][w],    bi = si[base + m][w];
            float cr = sr[base + 2*m][w],  ci = si[base + 2*m][w];
            float dr = sr[base + 3*m][w],  di = si[base + 3*m][w];
            float t0r = ar + cr, t0i = ai + ci;
            float t1r = ar - cr, t1i = ai - ci;
            float t2r = br + dr, t2i = bi + di;
            float t3r = br - dr, t3i = bi - di;
            sr[base][w] = t0r + t2r;  si[base][w] = t0i + t2i;
            float u1r = t1r + t3i, u1i = t1i - t3r;
            sr[base + m][w]   = u1r * w1.x - u1i * w1.y;
            si[base + m][w]   = u1r * w1.y + u1i * w1.x;
            float v2r = t0r - t2r, v2i = t0i - t2i;
            sr[base + 2*m][w] = v2r * w2.x - v2i * w2.y;
            si[base + 2*m][w] = v2r * w2.y + v2i * w2.x;
            float u3r = t1r - t3i, u3i = t1i + t3r;
            sr[base + 3*m][w] = u3r * w3.x - u3i * w3.y;
            si[base + 3*m][w] = u3r * w3.y + u3i * w3.x;
        }
        __syncwarp();
    }

    float va[5][4];
    #pragma unroll
    for (int r = 0; r < 4; ++r) {
        int k = l + 32 * r;
        int ik = dr4(k), im = dr4((256 - k) & 255);
        float zkr = sr[ik][w], zki = si[ik][w];
        float zmr = sr[im][w], zmi = si[im][w];
        va[r][0] = 0.5f * (zkr + zmr);
        va[r][1] = 0.5f * (zki - zmi);
        va[r][2] = 0.5f * (zki + zmi);
        va[r][3] = 0.5f * (zmr - zkr);
    }
    if (l == 0) {
        int ik = dr4(128);
        float zkr = sr[ik][w], zki = si[ik][w];
        va[4][0] = zkr; va[4][1] = 0.f;
        va[4][2] = zki; va[4][3] = 0.f;
    }

    // ---- fused stats: partial sum/sumsq over (c, c+16) x 129 k per t-col ----
    {
        float sA = 0.f, qA = 0.f, sB = 0.f, qB = 0.f;
        #pragma unroll
        for (int r = 0; r < 4; ++r) {
            sA += va[r][0] + va[r][1];
            qA = fmaf(va[r][0], va[r][0], qA); qA = fmaf(va[r][1], va[r][1], qA);
            sB += va[r][2] + va[r][3];
            qB = fmaf(va[r][2], va[r][2], qB); qB = fmaf(va[r][3], va[r][3], qB);
        }
        if (l == 0) {
            sA += va[4][0] + va[4][1];
            qA = fmaf(va[4][0], va[4][0], qA); qA = fmaf(va[4][1], va[4][1], qA);
            sB += va[4][2] + va[4][3];
            qB = fmaf(va[4][2], va[4][2], qB); qB = fmaf(va[4][3], va[4][3], qB);
        }
        #pragma unroll
        for (int off = 16; off; off >>= 1) {
            sA += __shfl_xor_sync(0xffffffffu, sA, off);
            qA += __shfl_xor_sync(0xffffffffu, qA, off);
            sB += __shfl_xor_sync(0xffffffffu, sB, off);
            qB += __shfl_xor_sync(0xffffffffu, qB, off);
        }
        if (l == 0) {
            int nA = b * 512 + t0 + 2 * w;
            g_psum[nA * 16 + c] = sA;       g_psq[nA * 16 + c] = qA;
            g_psum[(nA + 1) * 16 + c] = sB; g_psq[(nA + 1) * 16 + c] = qB;
        }
    }

    __syncwarp();
    #pragma unroll
    for (int r = 0; r < 4; ++r) {
        int k = l + 32 * r;
        sr[k][w] = va[r][0];        si[k][w] = va[r][1];
        sr[129 + k][w] = va[r][2];  si[129 + k][w] = va[r][3];
    }
    if (l == 0) {
        sr[128][w] = va[4][0];       si[128][w] = va[4][1];
        sr[129 + 128][w] = va[4][2]; si[129 + 128][w] = va[4][3];
    }
    __syncthreads();

    for (int i = tid; i < 4128; i += 512) {
        int k = i >> 5, tt = i & 31;
        int j = tt >> 1;
        int row = (tt & 1) ? (129 + k) : k;
        g_zraw[(((size_t)b * 32 + c)      * 129 + k) * 512 + t0 + tt] = sr[row][j];
        g_zraw[(((size_t)b * 32 + 16 + c) * 129 + k) * 512 + t0 + tt] = si[row][j];
    }
}

// ---------------- K2: finalize stats (16 partials per n) --------------------
__global__ void k_stats2() {
    int n = blockIdx.x * 256 + threadIdx.x;
    float S = 0.f, Q = 0.f;
    #pragma unroll
    for (int p = 0; p < 16; ++p) { S += g_psum[n * 16 + p]; Q += g_psq[n * 16 + p]; }
    float mean = S * (1.f / 4128.f);
    float var = (Q - S * mean) * (1.f / 4127.f);
    g_mean[n] = mean;
    g_rstd[n] = __fdividef(1.f, sqrtf(fmaxf(var, 0.f)) + 1e-8f);
}

// ---------------- K3: normalize + input-gate GEMM via tf32 mma.sync ---------
// grid (129, 64), block 256 (8 warps). tf32 pre-converted in smem.
__global__ void __launch_bounds__(256) k_gates(
    const float* __restrict__ nw, const float* __restrict__ nb,
    const float* __restrict__ wihf, const float* __restrict__ bihf, const float* __restrict__ bhhf,
    const float* __restrict__ wihb, const float* __restrict__ bihb, const float* __restrict__ bhhb) {
    int k = blockIdx.x;
    int n0 = blockIdx.y * 64;
    int b = n0 >> 9, tl0 = n0 & 511;
    __shared__ unsigned int ys[32][72];   // [q][t] tf32 bits after normalize
    __shared__ unsigned int ws[128][36];  // [gate][q] tf32 bits
    __shared__ float nws[32], nbs[32], means[64], rstds[64], bs[128];
    int tid = threadIdx.x;

    for (int i = tid; i < 2048; i += 256) {
        int c2 = i >> 6, tt = i & 63;
        ys[c2][tt] = __float_as_uint(g_zraw[(((size_t)b * 32 + c2) * 129 + k) * 512 + tl0 + tt]);
    }
    for (int i = tid; i < 4096; i += 256) {
        int g = i >> 5, q = i & 31;
        float wv = (g < 64) ? wihf[g * 32 + q] : wihb[(g - 64) * 32 + q];
        ws[g][q] = f2tf32(wv);
    }
    if (tid < 64) bs[tid] = bihf[tid] + bhhf[tid];
    else if (tid < 128) bs[tid] = bihb[tid - 64] + bhhb[tid - 64];
    if (tid < 32) { nws[tid] = nw[tid * 129 + k]; nbs[tid] = nb[tid * 129 + k]; }
    if (tid >= 128 && tid < 192) { means[tid - 128] = g_mean[n0 + tid - 128]; rstds[tid - 128] = g_rstd[n0 + tid - 128]; }
    __syncthreads();

    for (int i = tid; i < 2048; i += 256) {
        int c2 = i >> 6, tt = i & 63;
        float v = (__uint_as_float(ys[c2][tt]) - means[tt]) * rstds[tt] * nws[c2] + nbs[c2];
        ys[c2][tt] = f2tf32(v);
    }
    __syncthreads();

    int wid = tid >> 5, lane = tid & 31;
    int gid = lane >> 2, tid4 = lane & 3;
    int m_base = (wid & 3) << 4;          // 0,16,32,48
    int n_base0 = (wid >> 2) << 6;        // 0 or 64

    float acc[8][4];
    #pragma unroll
    for (int j = 0; j < 8; ++j) {
        int gb = n_base0 + j * 8 + tid4 * 2;
        acc[j][0] = bs[gb];     acc[j][1] = bs[gb + 1];
        acc[j][2] = bs[gb];     acc[j][3] = bs[gb + 1];
    }

    #pragma unroll
    for (int ks = 0; ks < 32; ks += 8) {
        // A frag: a0=A(g,t) a1=A(g+8,t) a2=A(g,t+4) a3=A(g+8,t+4)
        unsigned int a0 = ys[ks + tid4    ][m_base + gid];
        unsigned int a1 = ys[ks + tid4    ][m_base + gid + 8];
        unsigned int a2 = ys[ks + tid4 + 4][m_base + gid];
        unsigned int a3 = ys[ks + tid4 + 4][m_base + gid + 8];
        #pragma unroll
        for (int j = 0; j < 8; ++j) {
            int gb = n_base0 + j * 8 + gid;
            unsigned int b0 = ws[gb][ks + tid4];
            unsigned int b1 = ws[gb][ks + tid4 + 4];
            mma_tf32(acc[j], a0, a1, a2, a3, b0, b1);
        }
    }

    #pragma unroll
    for (int j = 0; j < 8; ++j) {
        int gate = n_base0 + j * 8 + tid4 * 2;
        int trow = n0 + m_base + gid;
        float2 v0 = make_float2(acc[j][0], acc[j][1]);
        float2 v1 = make_float2(acc[j][2], acc[j][3]);
        *reinterpret_cast<float2*>(&g_pre[((size_t)trow * 129 + k) * 128 + gate]) = v0;
        *reinterpret_cast<float2*>(&g_pre[((size_t)(trow + 8) * 129 + k) * 128 + gate]) = v1;
    }
}

// ---------------- K4: recurrent-only LSTM, one warp per (seq, dir) ----------
__global__ void __launch_bounds__(256) k_lstm(
    const float* __restrict__ whhf, const float* __restrict__ whhb) {
    int wg = blockIdx.x * 8 + (threadIdx.x >> 5);
    int lane = threadIdx.x & 31;
    int n = wg >> 1, dir = wg & 1;

    const float* whh = dir ? whhb : whhf;
    float wh0[16], wh1[16];
    #pragma unroll
    for (int q = 0; q < 16; ++q) {
        wh0[q] = whh[lane * 16 + q];
        wh1[q] = whh[(lane + 32) * 16 + q];
    }

    const float* pbase = g_pre + (size_t)n * 129 * 128 + dir * 64;
    float* hbase = g_h + (size_t)n * 129 * 32 + dir * 16;

    float h = 0.f, cst = 0.f;
    int k = dir ? 128 : 0;
    int stepd = dir ? -1 : 1;
    float p0 = pbase[k * 128 + lane];
    float p1 = pbase[k * 128 + 32 + lane];

    for (int s = 0; s < 129; ++s) {
        int kn = k + stepd;
        float np0 = 0.f, np1 = 0.f;
        if (s < 128) {
            np0 = pbase[kn * 128 + lane];
            np1 = pbase[kn * 128 + 32 + lane];
        }
        float a0 = p0, a1 = p1, c0 = 0.f, c1 = 0.f;
        #pragma unroll
        for (int q = 0; q < 8; ++q) {
            float hv = __shfl_sync(0xffffffffu, h, q);
            a0 = fmaf(hv, wh0[q], a0);
            a1 = fmaf(hv, wh1[q], a1);
        }
        #pragma unroll
        for (int q = 8; q < 16; ++q) {
            float hv = __shfl_sync(0xffffffffu, h, q);
            c0 = fmaf(hv, wh0[q], c0);
            c1 = fmaf(hv, wh1[q], c1);
        }
        a0 += c0; a1 += c1;
        float fo0 = __shfl_xor_sync(0xffffffffu, a0, 16);
        float fo1 = __shfl_xor_sync(0xffffffffu, a1, 16);
        if (lane < 16) {
            float ig = sigf(a0);
            float gg = tanhfast(a1);
            float ff = sigf(fo0);
            float oo = sigf(fo1);
            cst = fmaf(ff, cst, ig * gg);
            h = oo * tanhfast(cst);
            hbase[k * 32 + lane] = h;
        }
        p0 = np0; p1 = np1; k = kn;
    }
}

// ---------------- K5: linear(2H->2C) + complex multiply ---------------------
__global__ void k_lin_cmul(const float* __restrict__ lw, const float* __restrict__ lb) {
    int k = blockIdx.x, t0 = blockIdx.y * 32, b = blockIdx.z;
    __shared__ float hs[32][33];    // [t][j]
    __shared__ float lws[32][32];   // [c2][j]
    __shared__ float lbs[32];
    __shared__ float yls[32][33];   // [c2][t]
    int tid = threadIdx.x;

    for (int i = tid; i < 1024; i += 256) lws[i >> 5][i & 31] = lw[i];
    if (tid < 32) lbs[tid] = lb[tid];
    for (int i = tid; i < 1024; i += 256) {
        int tt = i >> 5, j = i & 31;
        hs[tt][j] = g_h[(((size_t)(b * 512 + t0 + tt)) * 129 + k) * 32 + j];
    }
    __syncthreads();

    int tt = tid & 31, g = tid >> 5;
    #pragma unroll
    for (int ci = 0; ci < 4; ++ci) {
        int c2 = g + ci * 8;
        float acc = lbs[c2];
        #pragma unroll
        for (int j = 0; j < 32; ++j) acc = fmaf(hs[tt][j], lws[c2][j], acc);
        yls[c2][tt] = acc;
    }
    __syncthreads();

    size_t basez = ((size_t)(b * 32) * 129 + k) * 512 + t0 + tt;
    const size_t ps = (size_t)129 * 512;
    #pragma unroll
    for (int ci = 0; ci < 4; ++ci) {
        int c2 = g + ci * 8;
        if (c2 < 16) {
            float xr = g_zraw[basez + (size_t)c2 * ps];
            float xi = g_zraw[basez + (size_t)(c2 + 16) * ps];
            float yr = yls[c2][tt], yi = yls[c2 + 16][tt];
            g_P[basez + (size_t)c2 * ps] = yr * xr - yi * xi;
        } else {
            int c = c2 - 16;
            float xr = g_zraw[basez + (size_t)c * ps];
            float xi = g_zraw[basez + (size_t)c2 * ps];
            float yr = yls[c][tt], yi = yls[c2][tt];
            g_P[basez + (size_t)c2 * ps] = yr * xi + yi * xr;
        }
    }
}

// ---------------- K6: irfft, warp-private radix-4, spectrum-pair packed -----
// grid (128, 16), block 512.
__global__ void __launch_bounds__(512) k_fft_inv(float* __restrict__ out) {
    int bc = blockIdx.x;
    int t0 = blockIdx.y * 32;
    int b = bc >> 4, c = bc & 15;
    __shared__ float sr[258][17], si[258][17];
    __shared__ float2 tw[192];
    int tid = threadIdx.x;
    int w = tid >> 5, l = tid & 31;

    if (tid < 192) {
        float sv, cv;
        __sincosf(6.28318530717958647692f * (float)tid * (1.f / 256.f), &sv, &cv);
        tw[tid] = make_float2(cv, sv);
    }
    for (int i = tid; i < 4128; i += 512) {
        int k = i >> 5, tt = i & 31;
        int j = tt >> 1;
        int row = (tt & 1) ? (129 + k) : k;
        sr[row][j] = g_P[(((size_t)b * 32 + c)      * 129 + k) * 512 + t0 + tt];
        si[row][j] = g_P[(((size_t)b * 32 + 16 + c) * 129 + k) * 512 + t0 + tt];
    }
    __syncthreads();

    float vz[8][2];
    #pragma unroll
    for (int r = 0; r < 8; ++r) {
        int row = l + 32 * r;
        float zr, zi;
        if (row <= 128) {
            float par = sr[row][w];
            float pai = (row == 0 || row == 128) ? 0.f : si[row][w];
            float pbr = sr[129 + row][w];
            float pbi = (row == 0 || row == 128) ? 0.f : si[129 + row][w];
            zr = par - pbi; zi = pai + pbr;
        } else {
            int m = 256 - row;
            float par = sr[m][w], pai = si[m][w];
            float pbr = sr[129 + m][w], pbi = si[129 + m][w];
            zr = par + pbi; zi = pbr - pai;
        }
        vz[r][0] = zr; vz[r][1] = zi;
    }
    __syncwarp();
    #pragma unroll
    for (int r = 0; r < 8; ++r) {
        int row = l + 32 * r;
        sr[row][w] = vz[r][0];
        si[row][w] = vz[r][1];
    }
    __syncwarp();

    #pragma unroll
    for (int stage = 0; stage < 4; ++stage) {
        int ms = 6 - 2 * stage;
        int m = 1 << ms;
        #pragma unroll
        for (int half = 0; half < 2; ++half) {
            int bfy = l + 32 * half;
            int g = bfy >> ms, p = bfy & (m - 1);
            int base = (g << (ms + 2)) + p;
            int e1 = p << (2 * stage);
            float2 w1 = tw[e1], w2 = tw[2 * e1], w3 = tw[3 * e1];
            float ar = sr[base][w],        ai = si[base][w];
            float br = sr[base + m][w],    bi = si[base + m][w];
            float cr = sr[base + 2*m][w],  ci = si[base + 2*m][w];
            float dr = sr[base + 3*m][w],  di = si[base + 3*m][w];
            float t0r = ar + cr, t0i = ai + ci;
            float t1r = ar - cr, t1i = ai - ci;
            float t2r = br + dr, t2i = bi + di;
            float t3r = br - dr, t3i = bi - di;
            sr[base][w] = t0r + t2r;  si[base][w] = t0i + t2i;
            float u1r = t1r - t3i, u1i = t1i + t3r;
            sr[base + m][w]   = u1r * w1.x - u1i * w1.y;
            si[base + m][w]   = u1r * w1.y + u1i * w1.x;
            float v2r = t0r - t2r, v2i = t0i - t2i;
            sr[base + 2*m][w] = v2r * w2.x - v2i * w2.y;
            si[base + 2*m][w] = v2r * w2.y + v2i * w2.x;
            float u3r = t1r + t3i, u3i = t1i - t3r;
            sr[base + 3*m][w] = u3r * w3.x - u3i * w3.y;
            si[base + 3*m][w] = u3r * w3.y + u3i * w3.x;
        }
        __syncwarp();
    }
    __syncthreads();

    const float inv = 1.f / 256.f;
    for (int i = tid; i < 8192; i += 512) {
        int f = i >> 5, tt = i & 31;
        int j = tt >> 1;
        int src = dr4(f);
        float v = (tt & 1) ? si[src][j] : sr[src][j];
        out[((size_t)bc * 256 + f) * 512 + t0 + tt] = v * inv;
    }
}

// ---------------- launcher ---------------------------------------------------
extern "C" void kernel_launch(void* const* d_in, const int* in_sizes, int n_in,
                              void* d_out, int out_size) {
    const float* x    = (const float*)d_in[0];
    const float* nw   = (const float*)d_in[1];
    const float* nb   = (const float*)d_in[2];
    const float* wihf = (const float*)d_in[3];
    const float* whhf = (const float*)d_in[4];
    const float* bihf = (const float*)d_in[5];
    const float* bhhf = (const float*)d_in[6];
    const float* wihb = (const float*)d_in[7];
    const float* whhb = (const float*)d_in[8];
    const float* bihb = (const float*)d_in[9];
    const float* bhhb = (const float*)d_in[10];
    const float* lw   = (const float*)d_in[11];
    const float* lb   = (const float*)d_in[12];
    float* out = (float*)d_out;

    k_fft_fwd<<<dim3(128, 16), 512>>>(x);
    k_stats2<<<16, 256>>>();
    k_gates<<<dim3(129, 64), 256>>>(nw, nb, wihf, bihf, bhhf, wihb, bihb, bhhb);
    k_lstm<<<1024, 256>>>(whhf, whhb);
    k_lin_cmul<<<dim3(129, 16, 8), 256>>>(lw, lb);
    k_fft_inv<<<dim3(128, 16), 512>>>(out);
}